// round 6
// baseline (speedup 1.0000x reference)
#include <cuda_runtime.h>
#include <cuda_bf16.h>
#include <math.h>
#include <stdint.h>

// ---------------------------------------------------------------------------
// B=2, C=128, HEADS=8, DH=16
// local 16x32x32 -> 16384 tok/batch, 256 windows of 64; global 8x16x16 -> 2048
// tok/batch, 256 windows of 8. TOPK=4 -> window attn over 64+32=96 tokens.
// GEMMs via mma.sync bf16 (HMMA) with 3-term bf16 split (K tripled):
//   A'' = [Ahi | Ahi | Alo]  (M x 3K),  W''t = [Whi | Wlo | Whi]  (N x 3K)
// ---------------------------------------------------------------------------

#define SCALE_DIM 0.08838834764831845f   // 128^-0.5
#define SCALE_DH  0.25f                  // 16^-0.5

// -------------------- static scratch (allocation-free) ---------------------
static __device__ float g_xg   [2*2048*128];
static __device__ float g_xl   [2*16384*128];
static __device__ float g_qkvg [2*2048*384];
static __device__ float g_xg4  [2*2048*128];
static __device__ float g_gwin [2*256*128];
static __device__ float g_qh   [2*256*128];
static __device__ float g_kh   [2*256*128];
static __device__ int   g_tidx [2*256*4];
static __device__ float g_sc   [2*256*96*128];
static __device__ float g_qkvp [2*256*96*384];
static __device__ float g_short[2*256*64*128];
static __device__ float g_lwin [2*256*64*128];
static __device__ float g_l    [2*16384*128];
static __device__ float g_lfin [2*16384*128];

// bf16 (stored as ushort) split activations / weights
static __device__ __align__(16) unsigned short g_a3_g   [4096u*384];
static __device__ __align__(16) unsigned short g_a3_attn[4096u*384];
static __device__ __align__(16) unsigned short g_a3_hid1[4096u*1536];
static __device__ __align__(16) unsigned short g_a3_sc  [49152u*384];
static __device__ __align__(16) unsigned short g_a3_awin[32768u*384];
static __device__ __align__(16) unsigned short g_a3_l   [32768u*384];
static __device__ __align__(16) unsigned short g_a3_hid2[32768u*1536];

static __device__ __align__(16) unsigned short g_w3_qkv [384u*384];
static __device__ __align__(16) unsigned short g_w3_proj[128u*384];
static __device__ __align__(16) unsigned short g_w3_mlp1[512u*384];
static __device__ __align__(16) unsigned short g_w3_mlp2[128u*1536];
static __device__ __align__(16) unsigned short g_w3_gqkv[384u*384];
static __device__ __align__(16) unsigned short g_w3_wo  [128u*384];
static __device__ __align__(16) unsigned short g_w3_m2w1[512u*384];
static __device__ __align__(16) unsigned short g_w3_m2w2[128u*1536];

// -------------------- helpers ----------------------------------------------
__device__ __forceinline__ uint32_t smem_u32(const void* p) {
    uint32_t a;
    asm("{ .reg .u64 t; cvta.to.shared.u64 t, %1; cvt.u32.u64 %0, t; }"
        : "=r"(a) : "l"(p));
    return a;
}
__device__ __forceinline__ void split2(float v, __nv_bfloat16& hi, __nv_bfloat16& lo) {
    hi = __float2bfloat16_rn(v);
    lo = __float2bfloat16_rn(v - __bfloat162float(hi));
}
__device__ __forceinline__ void ldmx4(uint32_t* r, uint32_t addr) {
    asm volatile("ldmatrix.sync.aligned.m8n8.x4.shared.b16 {%0,%1,%2,%3}, [%4];"
        : "=r"(r[0]), "=r"(r[1]), "=r"(r[2]), "=r"(r[3]) : "r"(addr));
}
__device__ __forceinline__ void mma16816(float* d, const uint32_t* a,
                                         uint32_t b0, uint32_t b1) {
    asm volatile(
        "mma.sync.aligned.m16n8k16.row.col.f32.bf16.bf16.f32 "
        "{%0,%1,%2,%3}, {%4,%5,%6,%7}, {%8,%9}, {%0,%1,%2,%3};"
        : "+f"(d[0]), "+f"(d[1]), "+f"(d[2]), "+f"(d[3])
        : "r"(a[0]), "r"(a[1]), "r"(a[2]), "r"(a[3]), "r"(b0), "r"(b1));
}

// -------------------- mma.sync GEMM ----------------------------------------
// C[M,N] = A''[M,K3] x W''t[N,K3]^T  (bf16 in, fp32 accum)
// tile 128x128, 256 threads (4x2 warps, each 32x64), K chunks of 64,
// single-buffer smem + register prefetch.
// mode 0: C = acc + bias (+res). mode 2: gelu(acc+bias) -> bf16-split Csplit.
__global__ __launch_bounds__(256)
void mma_gemm(const __nv_bfloat16* __restrict__ A3, const __nv_bfloat16* __restrict__ B3,
              const float* __restrict__ bias, const float* __restrict__ res,
              float* __restrict__ C, __nv_bfloat16* __restrict__ Csplit,
              int N, int K3, int mode)
{
    __shared__ __nv_bfloat16 As[128][72];
    __shared__ __nv_bfloat16 Bs[128][72];
    const int tid = threadIdx.x;
    const int lane = tid & 31, warp = tid >> 5;
    const int wm = warp >> 1, wn = warp & 1;          // 4 x 2 warp grid
    const int bm = blockIdx.y * 128, bn = blockIdx.x * 128;
    const int NC = K3 >> 6;

    const __nv_bfloat16* Abase = A3 + (size_t)bm * K3;
    const __nv_bfloat16* Bbase = B3 + (size_t)bn * K3;

    // per-thread global <-> smem mapping: idx = j*256+tid; row=idx>>3, c16=idx&7
    int grow[4], gc16[4];
    #pragma unroll
    for (int j = 0; j < 4; j++) {
        int idx = j * 256 + tid;
        grow[j] = idx >> 3;
        gc16[j] = idx & 7;
    }

    uint4 pa[4], pb[4];
    #pragma unroll
    for (int j = 0; j < 4; j++) {
        pa[j] = *(const uint4*)(Abase + (size_t)grow[j] * K3 + gc16[j] * 8);
        pb[j] = *(const uint4*)(Bbase + (size_t)grow[j] * K3 + gc16[j] * 8);
    }

    float acc[2][8][4];
    #pragma unroll
    for (int mt = 0; mt < 2; mt++)
        #pragma unroll
        for (int nt = 0; nt < 8; nt++)
            #pragma unroll
            for (int e = 0; e < 4; e++) acc[mt][nt][e] = 0.f;

    // ldmatrix addresses (row stride 144B; 8 rows hit distinct 16B windows)
    const uint32_t aAddr = smem_u32(&As[wm * 32 + (lane & 15)][(lane >> 4) * 8]);
    const int nrow = (lane & 7) + ((lane >> 4) << 3);
    const int bcol = ((lane >> 3) & 1) * 8;
    const uint32_t bAddr = smem_u32(&Bs[wn * 64 + nrow][bcol]);

    for (int c = 0; c < NC; c++) {
        #pragma unroll
        for (int j = 0; j < 4; j++) {
            *(uint4*)&As[grow[j]][gc16[j] * 8] = pa[j];
            *(uint4*)&Bs[grow[j]][gc16[j] * 8] = pb[j];
        }
        __syncthreads();
        if (c + 1 < NC) {
            const __nv_bfloat16* an = Abase + (c + 1) * 64;
            const __nv_bfloat16* bn2 = Bbase + (c + 1) * 64;
            #pragma unroll
            for (int j = 0; j < 4; j++) {
                pa[j] = *(const uint4*)(an + (size_t)grow[j] * K3 + gc16[j] * 8);
                pb[j] = *(const uint4*)(bn2 + (size_t)grow[j] * K3 + gc16[j] * 8);
            }
        }
        #pragma unroll
        for (int ks = 0; ks < 4; ks++) {
            uint32_t a[2][4], b[4][4];
            #pragma unroll
            for (int mt = 0; mt < 2; mt++)
                ldmx4(a[mt], aAddr + mt * 16 * 144 + ks * 32);
            #pragma unroll
            for (int p = 0; p < 4; p++)
                ldmx4(b[p], bAddr + p * 16 * 144 + ks * 32);
            #pragma unroll
            for (int mt = 0; mt < 2; mt++)
                #pragma unroll
                for (int nt = 0; nt < 8; nt++)
                    mma16816(acc[mt][nt], a[mt],
                             b[nt >> 1][(nt & 1) * 2], b[nt >> 1][(nt & 1) * 2 + 1]);
        }
        __syncthreads();
    }

    // epilogue
    const int tr = lane >> 2, tc = (lane & 3) * 2;
    #pragma unroll
    for (int mt = 0; mt < 2; mt++) {
        #pragma unroll
        for (int nt = 0; nt < 8; nt++) {
            int col = bn + wn * 64 + nt * 8 + tc;
            float bs0 = bias[col], bs1 = bias[col + 1];
            #pragma unroll
            for (int half = 0; half < 2; half++) {
                int row = bm + wm * 32 + mt * 16 + tr + half * 8;
                float v0 = acc[mt][nt][half * 2 + 0] + bs0;
                float v1 = acc[mt][nt][half * 2 + 1] + bs1;
                if (mode) {
                    v0 = 0.5f * v0 * (1.f + erff(v0 * 0.70710678118654752f));
                    v1 = 0.5f * v1 * (1.f + erff(v1 * 0.70710678118654752f));
                }
                if (mode == 2) {
                    __nv_bfloat16 h0, l0, h1, l1;
                    split2(v0, h0, l0); split2(v1, h1, l1);
                    size_t rb = (size_t)row * (3 * N);
                    Csplit[rb + col] = h0;           Csplit[rb + col + 1] = h1;
                    Csplit[rb + N + col] = h0;       Csplit[rb + N + col + 1] = h1;
                    Csplit[rb + 2 * N + col] = l0;   Csplit[rb + 2 * N + col + 1] = l1;
                } else {
                    size_t idx = (size_t)row * N + col;
                    if (res) { v0 += res[idx]; v1 += res[idx + 1]; }
                    C[idx] = v0; C[idx + 1] = v1;
                }
            }
        }
    }
}

// -------------------- weight split: W[K,N] -> W''t[N,3K] = [hi|lo|hi] ------
__global__ void w_split(const float* __restrict__ W, __nv_bfloat16* __restrict__ W3,
                        int K, int N)
{
    int idx = blockIdx.x * blockDim.x + threadIdx.x;
    if (idx >= K * N) return;
    int k = idx / N, n = idx % N;
    __nv_bfloat16 hi, lo;
    split2(W[(size_t)k * N + n], hi, lo);
    size_t rb = (size_t)n * 3 * K;
    W3[rb + k] = hi;
    W3[rb + K + k] = lo;
    W3[rb + 2 * K + k] = hi;
}

// -------------------- transpose: per-batch [R,Cc] -> [Cc,R] ----------------
__global__ void transpose2d(const float* __restrict__ in, float* __restrict__ out,
                            int R, int Cc)
{
    __shared__ float tile[32][33];
    size_t boff = (size_t)blockIdx.z * R * Cc;
    int c0 = blockIdx.x * 32, r0 = blockIdx.y * 32;
    int tx = threadIdx.x, ty = threadIdx.y;
    #pragma unroll
    for (int i = 0; i < 32; i += 8)
        tile[ty + i][tx] = in[boff + (size_t)(r0 + ty + i) * Cc + c0 + tx];
    __syncthreads();
    #pragma unroll
    for (int i = 0; i < 32; i += 8)
        out[boff + (size_t)(c0 + ty + i) * R + r0 + tx] = tile[tx][ty + i];
}

// -------------------- LayerNorm + bf16 split: x[ntok,128] -> y3[ntok,384] --
__global__ void ln_split(const float* __restrict__ x, const float* __restrict__ gam,
                         const float* __restrict__ bet, __nv_bfloat16* __restrict__ y3,
                         int ntok)
{
    int warp = (blockIdx.x * blockDim.x + threadIdx.x) >> 5;
    int lane = threadIdx.x & 31;
    if (warp >= ntok) return;
    const float4 xv = *(const float4*)(x + (size_t)warp * 128 + lane * 4);
    float s = xv.x + xv.y + xv.z + xv.w;
    #pragma unroll
    for (int o = 16; o; o >>= 1) s += __shfl_xor_sync(0xffffffffu, s, o);
    float mu = s * (1.f / 128.f);
    float dx = xv.x - mu, dy = xv.y - mu, dz = xv.z - mu, dw = xv.w - mu;
    float v = dx*dx + dy*dy + dz*dz + dw*dw;
    #pragma unroll
    for (int o = 16; o; o >>= 1) v += __shfl_xor_sync(0xffffffffu, v, o);
    float rs = rsqrtf(v * (1.f / 128.f) + 1e-6f);
    float4 gv = *(const float4*)(gam + lane * 4);
    float4 bv = *(const float4*)(bet + lane * 4);
    float ov[4];
    ov[0] = dx * rs * gv.x + bv.x;
    ov[1] = dy * rs * gv.y + bv.y;
    ov[2] = dz * rs * gv.z + bv.z;
    ov[3] = dw * rs * gv.w + bv.w;
    size_t base = (size_t)warp * 384 + lane * 4;
    #pragma unroll
    for (int i = 0; i < 4; i++) {
        __nv_bfloat16 hi, lo;
        split2(ov[i], hi, lo);
        y3[base + i] = hi;
        y3[base + 128 + i] = hi;
        y3[base + 256 + i] = lo;
    }
}

// -------------------- fp32 GEMM (small: rq/rk only) ------------------------
__global__ __launch_bounds__(256, 2)
void gemm_kernel(const float* __restrict__ A, const float* __restrict__ W,
                 const float* __restrict__ bias, const float* __restrict__ res,
                 float* __restrict__ C, int M, int N, int K, int act)
{
    __shared__ float As[16][132];
    __shared__ float Bs[16][132];
    const int bm = blockIdx.y * 128;
    const int bn = blockIdx.x * 128;
    const int tid = threadIdx.x;
    const int tx = tid & 15, ty = tid >> 4;
    const int arow = tid >> 1, acol = (tid & 1) * 8;
    const int brow = tid >> 4, bcol = (tid & 15) * 8;
    const float* Aptr = A + (size_t)(bm + arow) * K + acol;
    const float* Wptr = W + (size_t)brow * N + bn + bcol;
    float acc[8][8] = {};
    float4 a0 = *(const float4*)(Aptr);
    float4 a1 = *(const float4*)(Aptr + 4);
    float4 b0 = *(const float4*)(Wptr);
    float4 b1 = *(const float4*)(Wptr + 4);
    for (int k0 = 0; k0 < K; k0 += 16) {
        As[acol + 0][arow] = a0.x; As[acol + 1][arow] = a0.y;
        As[acol + 2][arow] = a0.z; As[acol + 3][arow] = a0.w;
        As[acol + 4][arow] = a1.x; As[acol + 5][arow] = a1.y;
        As[acol + 6][arow] = a1.z; As[acol + 7][arow] = a1.w;
        *(float4*)&Bs[brow][bcol] = b0;
        *(float4*)&Bs[brow][bcol + 4] = b1;
        __syncthreads();
        if (k0 + 16 < K) {
            a0 = *(const float4*)(Aptr + k0 + 16);
            a1 = *(const float4*)(Aptr + k0 + 20);
            b0 = *(const float4*)(Wptr + (size_t)(k0 + 16) * N);
            b1 = *(const float4*)(Wptr + (size_t)(k0 + 16) * N + 4);
        }
        #pragma unroll
        for (int kk = 0; kk < 16; kk++) {
            float a[8], b[8];
            *(float4*)(a)     = *(const float4*)&As[kk][ty * 4];
            *(float4*)(a + 4) = *(const float4*)&As[kk][64 + ty * 4];
            *(float4*)(b)     = *(const float4*)&Bs[kk][tx * 4];
            *(float4*)(b + 4) = *(const float4*)&Bs[kk][64 + tx * 4];
            #pragma unroll
            for (int i = 0; i < 8; i++)
                #pragma unroll
                for (int j = 0; j < 8; j++)
                    acc[i][j] += a[i] * b[j];
        }
        __syncthreads();
    }
    #pragma unroll
    for (int ih = 0; ih < 2; ih++)
        #pragma unroll
        for (int ii = 0; ii < 4; ii++) {
            int i = ih * 4 + ii;
            int row = bm + ih * 64 + ty * 4 + ii;
            #pragma unroll
            for (int jh = 0; jh < 2; jh++) {
                int col = bn + jh * 64 + tx * 4;
                float4 v;
                v.x = acc[i][jh * 4 + 0] + bias[col + 0];
                v.y = acc[i][jh * 4 + 1] + bias[col + 1];
                v.z = acc[i][jh * 4 + 2] + bias[col + 2];
                v.w = acc[i][jh * 4 + 3] + bias[col + 3];
                size_t idx = (size_t)row * N + col;
                if (res) {
                    float4 r4 = *(const float4*)(res + idx);
                    v.x += r4.x; v.y += r4.y; v.z += r4.z; v.w += r4.w;
                }
                *(float4*)(C + idx) = v;
            }
        }
}

// -------------------- global flash attention (split-bf16 epilogue) ---------
__global__ void attn_global(const float* __restrict__ qkv)
{
    const int b = blockIdx.z, h = blockIdx.y, q0 = blockIdx.x * 64;
    const int tid = threadIdx.x;
    const int q = tid >> 3, part = tid & 7;
    const float* base = qkv + (size_t)b * 2048 * 384;

    float4 qv[4];
    {
        const float4* qp = (const float4*)(base + (size_t)(q0 + q) * 384 + h * 16);
        #pragma unroll
        for (int i = 0; i < 4; i++) {
            qv[i] = qp[i];
            qv[i].x *= SCALE_DH; qv[i].y *= SCALE_DH;
            qv[i].z *= SCALE_DH; qv[i].w *= SCALE_DH;
        }
    }
    float m = -1e30f, l = 0.f;
    float o[16];
    #pragma unroll
    for (int d = 0; d < 16; d++) o[d] = 0.f;

    __shared__ float Ks[64][20];
    __shared__ float Vs[64][20];

    for (int c0 = 0; c0 < 2048; c0 += 64) {
        __syncthreads();
        {
            int mat = tid >> 8, idx = tid & 255;
            int r = idx >> 2, i = idx & 3;
            const float* row = base + (size_t)(c0 + r) * 384 + h * 16 + (mat ? 256 : 128);
            float* dst = mat ? Vs[r] : Ks[r];
            ((float4*)dst)[i] = *(const float4*)(row + i * 4);
        }
        __syncthreads();

        float s[8], cmax = -1e30f;
        #pragma unroll
        for (int j = 0; j < 8; j++) {
            int kr = part + j * 8;
            const float4* Kr = (const float4*)Ks[kr];
            float4 k0v = Kr[0], k1v = Kr[1], k2v = Kr[2], k3v = Kr[3];
            float a = qv[0].x*k0v.x + qv[0].y*k0v.y + qv[0].z*k0v.z + qv[0].w*k0v.w
                    + qv[1].x*k1v.x + qv[1].y*k1v.y + qv[1].z*k1v.z + qv[1].w*k1v.w
                    + qv[2].x*k2v.x + qv[2].y*k2v.y + qv[2].z*k2v.z + qv[2].w*k2v.w
                    + qv[3].x*k3v.x + qv[3].y*k3v.y + qv[3].z*k3v.z + qv[3].w*k3v.w;
            s[j] = a;
            cmax = fmaxf(cmax, a);
        }
        #pragma unroll
        for (int off = 4; off; off >>= 1)
            cmax = fmaxf(cmax, __shfl_xor_sync(0xffffffffu, cmax, off));
        float newm = fmaxf(m, cmax);
        float corr = __expf(m - newm);
        float p[8], psum = 0.f;
        #pragma unroll
        for (int j = 0; j < 8; j++) { p[j] = __expf(s[j] - newm); psum += p[j]; }
        #pragma unroll
        for (int off = 4; off; off >>= 1)
            psum += __shfl_xor_sync(0xffffffffu, psum, off);
        l = l * corr + psum;
        #pragma unroll
        for (int d = 0; d < 16; d++) o[d] *= corr;
        #pragma unroll
        for (int j = 0; j < 8; j++) {
            int kr = part + j * 8;
            const float4* Vr = (const float4*)Vs[kr];
            float4 v0 = Vr[0], v1 = Vr[1], v2 = Vr[2], v3 = Vr[3];
            float pj = p[j];
            o[0]  += pj * v0.x; o[1]  += pj * v0.y; o[2]  += pj * v0.z; o[3]  += pj * v0.w;
            o[4]  += pj * v1.x; o[5]  += pj * v1.y; o[6]  += pj * v1.z; o[7]  += pj * v1.w;
            o[8]  += pj * v2.x; o[9]  += pj * v2.y; o[10] += pj * v2.z; o[11] += pj * v2.w;
            o[12] += pj * v3.x; o[13] += pj * v3.y; o[14] += pj * v3.z; o[15] += pj * v3.w;
        }
        m = newm;
    }
    #pragma unroll
    for (int off = 4; off; off >>= 1)
        #pragma unroll
        for (int d = 0; d < 16; d++)
            o[d] += __shfl_xor_sync(0xffffffffu, o[d], off);
    float inv = 1.f / l;
    __nv_bfloat16* a3 = (__nv_bfloat16*)g_a3_attn;
    size_t row = (size_t)b * 2048 + q0 + q;
    int c = h * 16 + part * 2;
    #pragma unroll
    for (int d = 0; d < 2; d++) {
        __nv_bfloat16 hi, lo;
        split2(o[part * 2 + d] * inv, hi, lo);
        a3[row * 384 + c + d] = hi;
        a3[row * 384 + 128 + c + d] = hi;
        a3[row * 384 + 256 + c + d] = lo;
    }
}

// -------------------- window mean over global windows ----------------------
__global__ void gwin_kernel()
{
    int w = blockIdx.x, b = blockIdx.y, c = threadIdx.x;
    int i1 = w >> 6, i2 = (w >> 3) & 7, i3 = w & 7;
    float s = 0.f;
    #pragma unroll
    for (int ms = 0; ms < 2; ms++)
        #pragma unroll
        for (int mh = 0; mh < 2; mh++)
            #pragma unroll
            for (int mw = 0; mw < 2; mw++) {
                int n = (i1 * 2 + ms) * 256 + (i2 * 2 + mh) * 16 + (i3 * 2 + mw);
                s += g_xg4[((size_t)b * 2048 + n) * 128 + c];
            }
    g_gwin[((size_t)b * 256 + w) * 128 + c] = s * 0.125f;
}

// -------------------- routing: logits + top-4 indices ----------------------
__global__ void routing_kernel()
{
    int b = blockIdx.y, n = blockIdx.x, mIdx = threadIdx.x;
    __shared__ float lg[256];
    const float* qrow = g_qh + ((size_t)b * 256 + n) * 128;
    const float* krow = g_kh + ((size_t)b * 256 + mIdx) * 128;
    float acc = 0.f;
    #pragma unroll 8
    for (int c = 0; c < 128; c++) acc += qrow[c] * krow[c];
    lg[mIdx] = acc * SCALE_DIM;
    __syncthreads();
    if (mIdx == 0) {
        int* t = g_tidx + (b * 256 + n) * 4;
        for (int kk = 0; kk < 4; kk++) {
            float best = -1e30f; int bi = 0;
            for (int i = 0; i < 256; i++)
                if (lg[i] > best) { best = lg[i]; bi = i; }
            t[kk] = bi;
            lg[bi] = -1e30f;
        }
    }
}

// -------------------- gather: build sc [B,256,96,128] + shortcut -----------
__global__ void gather_kernel()
{
    int t = blockIdx.x, w = blockIdx.y, b = blockIdx.z, c = threadIdx.x;
    float v;
    if (t < 64) {
        int i1 = w >> 6, i2 = (w >> 3) & 7, i3 = w & 7;
        int ms = t >> 4, mh = (t >> 2) & 3, mw = t & 3;
        int n = (i1 * 4 + ms) * 1024 + (i2 * 4 + mh) * 32 + (i3 * 4 + mw);
        v = g_xl[((size_t)b * 16384 + n) * 128 + c];
        g_short[(((size_t)b * 256 + w) * 64 + t) * 128 + c] = v;
    } else {
        int tg = t - 64;
        int kk = tg >> 3, tt = tg & 7;
        int wg = g_tidx[(b * 256 + w) * 4 + kk];
        int j1 = wg >> 6, j2 = (wg >> 3) & 7, j3 = wg & 7;
        int ms = tt >> 2, mh = (tt >> 1) & 1, mw = tt & 1;
        int n = (j1 * 2 + ms) * 256 + (j2 * 2 + mh) * 16 + (j3 * 2 + mw);
        v = g_xg4[((size_t)b * 2048 + n) * 128 + c];
    }
    g_sc[(((size_t)b * 256 + w) * 96 + t) * 128 + c] = v;
}

// -------------------- window attention (split-bf16 epilogue) ---------------
__global__ void attn_win()
{
    const int w = blockIdx.x, h = blockIdx.y, b = blockIdx.z;
    const int tid = threadIdx.x;
    const float* base = g_qkvp + (size_t)(b * 256 + w) * 96 * 384;

    __shared__ float Ks[96][20];
    __shared__ float Vs[96][20];
    for (int e = tid; e < 384; e += 128) {
        int r = e >> 2, i = e & 3;
        const float* row = base + (size_t)r * 384 + h * 16;
        ((float4*)Ks[r])[i] = *(const float4*)(row + 128 + i * 4);
        ((float4*)Vs[r])[i] = *(const float4*)(row + 256 + i * 4);
    }
    __syncthreads();

    const int q = tid >> 1, part = tid & 1;
    float4 qv[4];
    {
        const float4* qp = (const float4*)(base + (size_t)q * 384 + h * 16);
        #pragma unroll
        for (int i = 0; i < 4; i++) {
            qv[i] = qp[i];
            qv[i].x *= SCALE_DIM; qv[i].y *= SCALE_DIM;
            qv[i].z *= SCALE_DIM; qv[i].w *= SCALE_DIM;
        }
    }
    float mx = -1e30f;
    for (int kr = part; kr < 96; kr += 2) {
        const float4* Kr = (const float4*)Ks[kr];
        float4 k0v = Kr[0], k1v = Kr[1], k2v = Kr[2], k3v = Kr[3];
        float a = qv[0].x*k0v.x + qv[0].y*k0v.y + qv[0].z*k0v.z + qv[0].w*k0v.w
                + qv[1].x*k1v.x + qv[1].y*k1v.y + qv[1].z*k1v.z + qv[1].w*k1v.w
                + qv[2].x*k2v.x + qv[2].y*k2v.y + qv[2].z*k2v.z + qv[2].w*k2v.w
                + qv[3].x*k3v.x + qv[3].y*k3v.y + qv[3].z*k3v.z + qv[3].w*k3v.w;
        mx = fmaxf(mx, a);
    }
    mx = fmaxf(mx, __shfl_xor_sync(0xffffffffu, mx, 1));
    float sum = 0.f;
    float o[16];
    #pragma unroll
    for (int d = 0; d < 16; d++) o[d] = 0.f;
    for (int kr = part; kr < 96; kr += 2) {
        const float4* Kr = (const float4*)Ks[kr];
        float4 k0v = Kr[0], k1v = Kr[1], k2v = Kr[2], k3v = Kr[3];
        float a = qv[0].x*k0v.x + qv[0].y*k0v.y + qv[0].z*k0v.z + qv[0].w*k0v.w
                + qv[1].x*k1v.x + qv[1].y*k1v.y + qv[1].z*k1v.z + qv[1].w*k1v.w
                + qv[2].x*k2v.x + qv[2].y*k2v.y + qv[2].z*k2v.z + qv[2].w*k2v.w
                + qv[3].x*k3v.x + qv[3].y*k3v.y + qv[3].z*k3v.z + qv[3].w*k3v.w;
        float p = __expf(a - mx);
        sum += p;
        const float4* Vr = (const float4*)Vs[kr];
        float4 v0 = Vr[0], v1 = Vr[1], v2 = Vr[2], v3 = Vr[3];
        o[0]  += p * v0.x; o[1]  += p * v0.y; o[2]  += p * v0.z; o[3]  += p * v0.w;
        o[4]  += p * v1.x; o[5]  += p * v1.y; o[6]  += p * v1.z; o[7]  += p * v1.w;
        o[8]  += p * v2.x; o[9]  += p * v2.y; o[10] += p * v2.z; o[11] += p * v2.w;
        o[12] += p * v3.x; o[13] += p * v3.y; o[14] += p * v3.z; o[15] += p * v3.w;
    }
    sum += __shfl_xor_sync(0xffffffffu, sum, 1);
    #pragma unroll
    for (int d = 0; d < 16; d++) o[d] += __shfl_xor_sync(0xffffffffu, o[d], 1);
    float inv = 1.f / sum;
    __nv_bfloat16* a3 = (__nv_bfloat16*)g_a3_awin;
    size_t row = ((size_t)(b * 256 + w)) * 64 + q;
    int cb = h * 16 + part * 8;
    #pragma unroll
    for (int d = 0; d < 8; d++) {
        __nv_bfloat16 hi, lo;
        split2(o[part * 8 + d] * inv, hi, lo);
        a3[row * 384 + cb + d] = hi;
        a3[row * 384 + 128 + cb + d] = hi;
        a3[row * 384 + 256 + cb + d] = lo;
    }
}

// -------------------- un-window: g_lwin -> g_l -----------------------------
__global__ void unwindow_kernel()
{
    int t = blockIdx.x, w = blockIdx.y, b = blockIdx.z, c = threadIdx.x;
    int i1 = w >> 6, i2 = (w >> 3) & 7, i3 = w & 7;
    int ms = t >> 4, mh = (t >> 2) & 3, mw = t & 3;
    int n = (i1 * 4 + ms) * 1024 + (i2 * 4 + mh) * 32 + (i3 * 4 + mw);
    g_l[((size_t)b * 16384 + n) * 128 + c] =
        g_lwin[(((size_t)b * 256 + w) * 64 + t) * 128 + c];
}

// ---------------------------------------------------------------------------
extern "C" void kernel_launch(void* const* d_in, const int* in_sizes, int n_in,
                              void* d_out, int out_size)
{
    const float* x_in    = (const float*)d_in[0];
    const float* x_g_in  = (const float*)d_in[1];
    const float* qkv_w   = (const float*)d_in[2];
    const float* qkv_b   = (const float*)d_in[3];
    const float* proj_w  = (const float*)d_in[4];
    const float* proj_b  = (const float*)d_in[5];
    const float* ln_g    = (const float*)d_in[6];
    const float* ln_b    = (const float*)d_in[7];
    const float* mlp_w1  = (const float*)d_in[8];
    const float* mlp_b1  = (const float*)d_in[9];
    const float* mlp_w2  = (const float*)d_in[10];
    const float* mlp_b2  = (const float*)d_in[11];
    const float* rq_w    = (const float*)d_in[12];
    const float* rq_b    = (const float*)d_in[13];
    const float* rk_w    = (const float*)d_in[14];
    const float* rk_b    = (const float*)d_in[15];
    const float* gqkv_w  = (const float*)d_in[16];
    const float* gqkv_b  = (const float*)d_in[17];
    const float* wo_w    = (const float*)d_in[18];
    const float* wo_b    = (const float*)d_in[19];
    const float* mlp2_w1 = (const float*)d_in[20];
    const float* mlp2_b1 = (const float*)d_in[21];
    const float* mlp2_w2 = (const float*)d_in[22];
    const float* mlp2_b2 = (const float*)d_in[23];
    float* out = (float*)d_out;

    float *xg, *xl, *qkvg, *xg4, *gwin, *qh, *kh, *sc, *qkvp, *shortc, *lwin, *lbuf, *lfin;
    cudaGetSymbolAddress((void**)&xg,    g_xg);
    cudaGetSymbolAddress((void**)&xl,    g_xl);
    cudaGetSymbolAddress((void**)&qkvg,  g_qkvg);
    cudaGetSymbolAddress((void**)&xg4,   g_xg4);
    cudaGetSymbolAddress((void**)&gwin,  g_gwin);
    cudaGetSymbolAddress((void**)&qh,    g_qh);
    cudaGetSymbolAddress((void**)&kh,    g_kh);
    cudaGetSymbolAddress((void**)&sc,    g_sc);
    cudaGetSymbolAddress((void**)&qkvp,  g_qkvp);
    cudaGetSymbolAddress((void**)&shortc,g_short);
    cudaGetSymbolAddress((void**)&lwin,  g_lwin);
    cudaGetSymbolAddress((void**)&lbuf,  g_l);
    cudaGetSymbolAddress((void**)&lfin,  g_lfin);

    __nv_bfloat16 *a3g, *a3attn, *a3hid1, *a3sc, *a3awin, *a3l, *a3hid2;
    __nv_bfloat16 *w3qkv, *w3proj, *w3mlp1, *w3mlp2, *w3gqkv, *w3wo, *w3m2w1, *w3m2w2;
    cudaGetSymbolAddress((void**)&a3g,    g_a3_g);
    cudaGetSymbolAddress((void**)&a3attn, g_a3_attn);
    cudaGetSymbolAddress((void**)&a3hid1, g_a3_hid1);
    cudaGetSymbolAddress((void**)&a3sc,   g_a3_sc);
    cudaGetSymbolAddress((void**)&a3awin, g_a3_awin);
    cudaGetSymbolAddress((void**)&a3l,    g_a3_l);
    cudaGetSymbolAddress((void**)&a3hid2, g_a3_hid2);
    cudaGetSymbolAddress((void**)&w3qkv,  g_w3_qkv);
    cudaGetSymbolAddress((void**)&w3proj, g_w3_proj);
    cudaGetSymbolAddress((void**)&w3mlp1, g_w3_mlp1);
    cudaGetSymbolAddress((void**)&w3mlp2, g_w3_mlp2);
    cudaGetSymbolAddress((void**)&w3gqkv, g_w3_gqkv);
    cudaGetSymbolAddress((void**)&w3wo,   g_w3_wo);
    cudaGetSymbolAddress((void**)&w3m2w1, g_w3_m2w1);
    cudaGetSymbolAddress((void**)&w3m2w2, g_w3_m2w2);

    dim3 tb(32, 8);

    // 0) weight splits
    w_split<<<(128*384+255)/256, 256>>>(qkv_w,   w3qkv,  128, 384);
    w_split<<<(128*128+255)/256, 256>>>(proj_w,  w3proj, 128, 128);
    w_split<<<(128*512+255)/256, 256>>>(mlp_w1,  w3mlp1, 128, 512);
    w_split<<<(512*128+255)/256, 256>>>(mlp_w2,  w3mlp2, 512, 128);
    w_split<<<(128*384+255)/256, 256>>>(gqkv_w,  w3gqkv, 128, 384);
    w_split<<<(128*128+255)/256, 256>>>(wo_w,    w3wo,   128, 128);
    w_split<<<(128*512+255)/256, 256>>>(mlp2_w1, w3m2w1, 128, 512);
    w_split<<<(512*128+255)/256, 256>>>(mlp2_w2, w3m2w2, 512, 128);

    // 1) transposes to token-major
    transpose2d<<<dim3(2048 / 32, 4, 2), tb>>>(x_g_in, xg, 128, 2048);
    transpose2d<<<dim3(16384 / 32, 4, 2), tb>>>(x_in, xl, 128, 16384);

    // 2) global branch
    ln_split<<<512, 256>>>(xg, ln_g, ln_b, a3g, 4096);
    mma_gemm<<<dim3(3, 32), 256>>>(a3g, w3qkv, qkv_b, nullptr, qkvg, nullptr, 384, 384, 0);
    attn_global<<<dim3(32, 8, 2), 512>>>(qkvg);
    mma_gemm<<<dim3(1, 32), 256>>>(a3attn, w3proj, proj_b, xg, xg, nullptr, 128, 384, 0);
    ln_split<<<512, 256>>>(xg, ln_g, ln_b, a3g, 4096);
    mma_gemm<<<dim3(4, 32), 256>>>(a3g, w3mlp1, mlp_b1, nullptr, nullptr, a3hid1, 512, 384, 2);
    mma_gemm<<<dim3(1, 32), 256>>>(a3hid1, w3mlp2, mlp_b2, xg, xg4, nullptr, 128, 1536, 0);

    // 3) routing
    gwin_kernel<<<dim3(256, 2), 128>>>();
    gemm_kernel<<<dim3(1, 4), 256>>>(gwin, rq_w, rq_b, nullptr, qh, 512, 128, 128, 0);
    gemm_kernel<<<dim3(1, 4), 256>>>(gwin, rk_w, rk_b, nullptr, kh, 512, 128, 128, 0);
    routing_kernel<<<dim3(256, 2), 256>>>();

    // 4) gather -> LN -> gqkv -> window attention
    gather_kernel<<<dim3(96, 256, 2), 128>>>();
    ln_split<<<6144, 256>>>(sc, ln_g, ln_b, a3sc, 49152);
    mma_gemm<<<dim3(3, 384), 256>>>(a3sc, w3gqkv, gqkv_b, nullptr, qkvp, nullptr, 384, 384, 0);
    attn_win<<<dim3(256, 8, 2), 128>>>();

    // 5) wo(+shortcut) -> un-window -> LN -> MLP2(+res)
    mma_gemm<<<dim3(1, 256), 256>>>(a3awin, w3wo, wo_b, shortc, lwin, nullptr, 128, 384, 0);
    unwindow_kernel<<<dim3(64, 256, 2), 128>>>();
    ln_split<<<4096, 256>>>(lbuf, ln_g, ln_b, a3l, 32768);
    mma_gemm<<<dim3(4, 256), 256>>>(a3l, w3m2w1, mlp2_b1, nullptr, nullptr, a3hid2, 512, 384, 2);
    mma_gemm<<<dim3(1, 256), 256>>>(a3hid2, w3m2w2, mlp2_b2, lbuf, lfin, nullptr, 128, 1536, 0);

    // 6) outputs
    transpose2d<<<dim3(4, 16384 / 32, 2), tb>>>(lfin, out, 16384, 128);
    transpose2d<<<dim3(4, 2048 / 32, 2), tb>>>(xg4, out + 2 * 128 * 16384, 2048, 128);
}

// round 9
// speedup vs baseline: 1.0803x; 1.0803x over previous
#include <cuda_runtime.h>
#include <cuda_bf16.h>
#include <math.h>
#include <stdint.h>

// ---------------------------------------------------------------------------
// B=2, C=128, HEADS=8, DH=16
// local 16x32x32 -> 16384 tok/batch, 256 windows of 64; global 8x16x16 -> 2048
// tok/batch, 256 windows of 8. TOPK=4 -> window attn over 64+32=96 tokens.
// GEMMs via mma.sync bf16 (HMMA) with 3-term bf16 split (K tripled):
//   A'' = [Ahi | Ahi | Alo]  (M x 3K),  W''t = [Whi | Wlo | Whi]  (N x 3K)
// ---------------------------------------------------------------------------

#define SCALE_DIM 0.08838834764831845f   // 128^-0.5
#define SCALE_DH  0.25f                  // 16^-0.5

// -------------------- static scratch (allocation-free) ---------------------
static __device__ float g_xg   [2*2048*128];
static __device__ float g_xl   [2*16384*128];
static __device__ float g_qkvg [2*2048*384];
static __device__ float g_xg4  [2*2048*128];
static __device__ float g_gwin [2*256*128];
static __device__ float g_qh   [2*256*128];
static __device__ float g_kh   [2*256*128];
static __device__ int   g_tidx [2*256*4];
static __device__ float g_qkvp [2*256*96*384];
static __device__ float g_short[2*256*64*128];
static __device__ float g_lwin [2*256*64*128];
static __device__ float g_l    [2*16384*128];
static __device__ float g_lfin [2*16384*128];

// bf16 (stored as ushort) split activations / weights
static __device__ __align__(16) unsigned short g_a3_g   [4096u*384];
static __device__ __align__(16) unsigned short g_a3_attn[4096u*384];
static __device__ __align__(16) unsigned short g_a3_hid1[4096u*1536];
static __device__ __align__(16) unsigned short g_a3_sc  [49152u*384];
static __device__ __align__(16) unsigned short g_a3_awin[32768u*384];
static __device__ __align__(16) unsigned short g_a3_l   [32768u*384];
static __device__ __align__(16) unsigned short g_a3_hid2[32768u*1536];

static __device__ __align__(16) unsigned short g_w3_qkv [384u*384];
static __device__ __align__(16) unsigned short g_w3_proj[128u*384];
static __device__ __align__(16) unsigned short g_w3_mlp1[512u*384];
static __device__ __align__(16) unsigned short g_w3_mlp2[128u*1536];
static __device__ __align__(16) unsigned short g_w3_gqkv[384u*384];
static __device__ __align__(16) unsigned short g_w3_wo  [128u*384];
static __device__ __align__(16) unsigned short g_w3_m2w1[512u*384];
static __device__ __align__(16) unsigned short g_w3_m2w2[128u*1536];

// -------------------- helpers ----------------------------------------------
__device__ __forceinline__ uint32_t smem_u32(const void* p) {
    uint32_t a;
    asm("{ .reg .u64 t; cvta.to.shared.u64 t, %1; cvt.u32.u64 %0, t; }"
        : "=r"(a) : "l"(p));
    return a;
}
__device__ __forceinline__ void split2(float v, __nv_bfloat16& hi, __nv_bfloat16& lo) {
    hi = __float2bfloat16_rn(v);
    lo = __float2bfloat16_rn(v - __bfloat162float(hi));
}
__device__ __forceinline__ void ldmx4(uint32_t* r, uint32_t addr) {
    asm volatile("ldmatrix.sync.aligned.m8n8.x4.shared.b16 {%0,%1,%2,%3}, [%4];"
        : "=r"(r[0]), "=r"(r[1]), "=r"(r[2]), "=r"(r[3]) : "r"(addr));
}
__device__ __forceinline__ void mma16816(float* d, const uint32_t* a,
                                         uint32_t b0, uint32_t b1) {
    asm volatile(
        "mma.sync.aligned.m16n8k16.row.col.f32.bf16.bf16.f32 "
        "{%0,%1,%2,%3}, {%4,%5,%6,%7}, {%8,%9}, {%0,%1,%2,%3};"
        : "+f"(d[0]), "+f"(d[1]), "+f"(d[2]), "+f"(d[3])
        : "r"(a[0]), "r"(a[1]), "r"(a[2]), "r"(a[3]), "r"(b0), "r"(b1));
}
__device__ __forceinline__ void cp16(uint32_t smem, const void* g) {
    asm volatile("cp.async.cg.shared.global [%0], [%1], 16;" :: "r"(smem), "l"(g));
}
#define CP_COMMIT() asm volatile("cp.async.commit_group;" ::: "memory")
#define CP_WAIT0()  asm volatile("cp.async.wait_group 0;" ::: "memory")
#define CP_WAIT1()  asm volatile("cp.async.wait_group 1;" ::: "memory")

// -------------------- mma.sync GEMM (cp.async 2-stage) ---------------------
// C[M,N] = A''[M,K3] x W''t[N,K3]^T (bf16 in, fp32 accum)
// tile 128x128, 256 threads (4x2 warps, each 32x64), K chunks of 64.
// dyn smem: A[2] + B[2] matrices of 128x72 bf16 (18432 B each) -> 73728 B.
// mode 0: C = acc + bias (+res). mode 2: gelu(acc+bias) -> bf16-split Csplit.
#define GSM_BYTES 73728
#define A_OFF(buf) ((buf) * 18432)
#define B_OFF(buf) (36864 + (buf) * 18432)

__global__ __launch_bounds__(256)
void mma_gemm(const __nv_bfloat16* __restrict__ A3, const __nv_bfloat16* __restrict__ B3,
              const float* __restrict__ bias, const float* __restrict__ res,
              float* __restrict__ C, __nv_bfloat16* __restrict__ Csplit,
              int N, int K3, int mode)
{
    extern __shared__ __nv_bfloat16 dsm[];
    const uint32_t smbase = smem_u32(dsm);
    const int tid = threadIdx.x;
    const int lane = tid & 31, warp = tid >> 5;
    const int wm = warp >> 1, wn = warp & 1;          // 4 x 2 warp grid
    const int bm = blockIdx.y * 128, bn = blockIdx.x * 128;
    const int NC = K3 >> 6;

    const __nv_bfloat16* Abase = A3 + (size_t)bm * K3;
    const __nv_bfloat16* Bbase = B3 + (size_t)bn * K3;

    // per-thread load mapping: idx = j*256+tid; row=idx>>3, c16=idx&7
    int grow[4], gc16[4];
    uint32_t soff[4];
    #pragma unroll
    for (int j = 0; j < 4; j++) {
        int idx = j * 256 + tid;
        grow[j] = idx >> 3;
        gc16[j] = idx & 7;
        soff[j] = (uint32_t)(grow[j] * 72 + gc16[j] * 8) * 2;  // bytes within matrix
    }

    float acc[2][8][4];
    #pragma unroll
    for (int mt = 0; mt < 2; mt++)
        #pragma unroll
        for (int nt = 0; nt < 8; nt++)
            #pragma unroll
            for (int e = 0; e < 4; e++) acc[mt][nt][e] = 0.f;

    // ldmatrix lane offsets (bytes; row stride 144B)
    const uint32_t aOffL = (uint32_t)((wm * 32 + (lane & 15)) * 72 + (lane >> 4) * 8) * 2;
    const int nrow = (lane & 7) + ((lane >> 4) << 3);
    const uint32_t bOffL = (uint32_t)((wn * 64 + nrow) * 72 + ((lane >> 3) & 1) * 8) * 2;

    // preload chunk 0 -> buf 0
    #pragma unroll
    for (int j = 0; j < 4; j++) {
        cp16(smbase + A_OFF(0) + soff[j], Abase + (size_t)grow[j] * K3 + gc16[j] * 8);
        cp16(smbase + B_OFF(0) + soff[j], Bbase + (size_t)grow[j] * K3 + gc16[j] * 8);
    }
    CP_COMMIT();

    for (int c = 0; c < NC; c++) {
        const int buf = c & 1;
        if (c + 1 < NC) {
            const int nb = (c + 1) & 1;
            const __nv_bfloat16* an = Abase + (c + 1) * 64;
            const __nv_bfloat16* bp = Bbase + (c + 1) * 64;
            #pragma unroll
            for (int j = 0; j < 4; j++) {
                cp16(smbase + A_OFF(nb) + soff[j], an + (size_t)grow[j] * K3 + gc16[j] * 8);
                cp16(smbase + B_OFF(nb) + soff[j], bp + (size_t)grow[j] * K3 + gc16[j] * 8);
            }
            CP_COMMIT();
            CP_WAIT1();
        } else {
            CP_WAIT0();
        }
        __syncthreads();
        const uint32_t aAddr = smbase + A_OFF(buf) + aOffL;
        const uint32_t bAddr = smbase + B_OFF(buf) + bOffL;
        #pragma unroll
        for (int ks = 0; ks < 4; ks++) {
            uint32_t a[2][4], b[4][4];
            #pragma unroll
            for (int mt = 0; mt < 2; mt++)
                ldmx4(a[mt], aAddr + mt * 16 * 144 + ks * 32);
            #pragma unroll
            for (int p = 0; p < 4; p++)
                ldmx4(b[p], bAddr + p * 16 * 144 + ks * 32);
            #pragma unroll
            for (int mt = 0; mt < 2; mt++)
                #pragma unroll
                for (int nt = 0; nt < 8; nt++)
                    mma16816(acc[mt][nt], a[mt],
                             b[nt >> 1][(nt & 1) * 2], b[nt >> 1][(nt & 1) * 2 + 1]);
        }
        __syncthreads();
    }

    // epilogue
    const int tr = lane >> 2, tc = (lane & 3) * 2;
    #pragma unroll
    for (int mt = 0; mt < 2; mt++) {
        #pragma unroll
        for (int nt = 0; nt < 8; nt++) {
            int col = bn + wn * 64 + nt * 8 + tc;
            float bs0 = bias[col], bs1 = bias[col + 1];
            #pragma unroll
            for (int half = 0; half < 2; half++) {
                int row = bm + wm * 32 + mt * 16 + tr + half * 8;
                float v0 = acc[mt][nt][half * 2 + 0] + bs0;
                float v1 = acc[mt][nt][half * 2 + 1] + bs1;
                if (mode) {
                    v0 = 0.5f * v0 * (1.f + erff(v0 * 0.70710678118654752f));
                    v1 = 0.5f * v1 * (1.f + erff(v1 * 0.70710678118654752f));
                }
                if (mode == 2) {
                    __nv_bfloat16 h0, l0, h1, l1;
                    split2(v0, h0, l0); split2(v1, h1, l1);
                    size_t rb = (size_t)row * (3 * N);
                    Csplit[rb + col] = h0;           Csplit[rb + col + 1] = h1;
                    Csplit[rb + N + col] = h0;       Csplit[rb + N + col + 1] = h1;
                    Csplit[rb + 2 * N + col] = l0;   Csplit[rb + 2 * N + col + 1] = l1;
                } else {
                    size_t idx = (size_t)row * N + col;
                    if (res) { v0 += res[idx]; v1 += res[idx + 1]; }
                    C[idx] = v0; C[idx + 1] = v1;
                }
            }
        }
    }
}

// -------------------- merged weight split (1 launch, 8 segments) -----------
// W[K,N] -> W''t[N,3K] = [hi | lo | hi]
__global__ void w_split_all(const float* w0, const float* w1, const float* w2,
                            const float* w3, const float* w4, const float* w5,
                            const float* w6, const float* w7,
                            __nv_bfloat16* o0, __nv_bfloat16* o1, __nv_bfloat16* o2,
                            __nv_bfloat16* o3, __nv_bfloat16* o4, __nv_bfloat16* o5,
                            __nv_bfloat16* o6, __nv_bfloat16* o7)
{
    const float* W; __nv_bfloat16* O; int K, N;
    switch (blockIdx.y) {
        case 0: W = w0; O = o0; K = 128; N = 384; break;
        case 1: W = w1; O = o1; K = 128; N = 128; break;
        case 2: W = w2; O = o2; K = 128; N = 512; break;
        case 3: W = w3; O = o3; K = 512; N = 128; break;
        case 4: W = w4; O = o4; K = 128; N = 384; break;
        case 5: W = w5; O = o5; K = 128; N = 128; break;
        case 6: W = w6; O = o6; K = 128; N = 512; break;
        default:W = w7; O = o7; K = 512; N = 128; break;
    }
    int idx = blockIdx.x * blockDim.x + threadIdx.x;
    if (idx >= K * N) return;
    int k = idx / N, n = idx % N;
    __nv_bfloat16 hi, lo;
    split2(W[(size_t)k * N + n], hi, lo);
    size_t rb = (size_t)n * 3 * K;
    O[rb + k] = hi;
    O[rb + K + k] = lo;
    O[rb + 2 * K + k] = hi;
}

// -------------------- transpose: per-batch [R,Cc] -> [Cc,R] ----------------
__global__ void transpose2d(const float* __restrict__ in, float* __restrict__ out,
                            int R, int Cc)
{
    __shared__ float tile[32][33];
    size_t boff = (size_t)blockIdx.z * R * Cc;
    int c0 = blockIdx.x * 32, r0 = blockIdx.y * 32;
    int tx = threadIdx.x, ty = threadIdx.y;
    #pragma unroll
    for (int i = 0; i < 32; i += 8)
        tile[ty + i][tx] = in[boff + (size_t)(r0 + ty + i) * Cc + c0 + tx];
    __syncthreads();
    #pragma unroll
    for (int i = 0; i < 32; i += 8)
        out[boff + (size_t)(c0 + ty + i) * R + r0 + tx] = tile[tx][ty + i];
}

// -------------------- warp LN + bf16-split write helper --------------------
__device__ __forceinline__ void warp_ln_split(float4 xv, const float* gam,
                                              const float* bet, int lane,
                                              __nv_bfloat16* dst_row)
{
    float s = xv.x + xv.y + xv.z + xv.w;
    #pragma unroll
    for (int o = 16; o; o >>= 1) s += __shfl_xor_sync(0xffffffffu, s, o);
    float mu = s * (1.f / 128.f);
    float dx = xv.x - mu, dy = xv.y - mu, dz = xv.z - mu, dw = xv.w - mu;
    float v = dx*dx + dy*dy + dz*dz + dw*dw;
    #pragma unroll
    for (int o = 16; o; o >>= 1) v += __shfl_xor_sync(0xffffffffu, v, o);
    float rs = rsqrtf(v * (1.f / 128.f) + 1e-6f);
    float4 gv = *(const float4*)(gam + lane * 4);
    float4 bv = *(const float4*)(bet + lane * 4);
    float ov[4];
    ov[0] = dx * rs * gv.x + bv.x;
    ov[1] = dy * rs * gv.y + bv.y;
    ov[2] = dz * rs * gv.z + bv.z;
    ov[3] = dw * rs * gv.w + bv.w;
    #pragma unroll
    for (int i = 0; i < 4; i++) {
        __nv_bfloat16 hi, lo;
        split2(ov[i], hi, lo);
        dst_row[lane * 4 + i] = hi;
        dst_row[128 + lane * 4 + i] = hi;
        dst_row[256 + lane * 4 + i] = lo;
    }
}

// -------------------- LayerNorm + split: x[ntok,128] -> y3[ntok,384] -------
__global__ void ln_split(const float* __restrict__ x, const float* __restrict__ gam,
                         const float* __restrict__ bet, __nv_bfloat16* __restrict__ y3,
                         int ntok)
{
    int warp = (blockIdx.x * blockDim.x + threadIdx.x) >> 5;
    int lane = threadIdx.x & 31;
    if (warp >= ntok) return;
    float4 xv = *(const float4*)(x + (size_t)warp * 128 + lane * 4);
    warp_ln_split(xv, gam, bet, lane, y3 + (size_t)warp * 384);
}

// -------------------- fused gather + LN + split ----------------------------
// token t of window w: t<64 local (also save raw to g_short), t>=64 routed global.
// out: a3sc row. grid (12, 256, 2) x 256 thr (8 warps = 8 tokens).
__global__ void gather_ln(const float* __restrict__ gam, const float* __restrict__ bet)
{
    int warp = threadIdx.x >> 5, lane = threadIdx.x & 31;
    int t = blockIdx.x * 8 + warp;
    int w = blockIdx.y, b = blockIdx.z;
    const float* src;
    if (t < 64) {
        int i1 = w >> 6, i2 = (w >> 3) & 7, i3 = w & 7;
        int ms = t >> 4, mh = (t >> 2) & 3, mw = t & 3;
        int n = (i1 * 4 + ms) * 1024 + (i2 * 4 + mh) * 32 + (i3 * 4 + mw);
        src = g_xl + ((size_t)b * 16384 + n) * 128;
    } else {
        int tg = t - 64;
        int kk = tg >> 3, tt = tg & 7;
        int wg = g_tidx[(b * 256 + w) * 4 + kk];
        int j1 = wg >> 6, j2 = (wg >> 3) & 7, j3 = wg & 7;
        int ms = tt >> 2, mh = (tt >> 1) & 1, mw = tt & 1;
        int n = (j1 * 2 + ms) * 256 + (j2 * 2 + mh) * 16 + (j3 * 2 + mw);
        src = g_xg4 + ((size_t)b * 2048 + n) * 128;
    }
    float4 xv = *(const float4*)(src + lane * 4);
    if (t < 64)
        *(float4*)(g_short + (((size_t)b * 256 + w) * 64 + t) * 128 + lane * 4) = xv;
    size_t row = ((size_t)b * 256 + w) * 96 + t;
    warp_ln_split(xv, gam, bet, lane, (__nv_bfloat16*)g_a3_sc + row * 384);
}

// -------------------- fused unwindow + LN + split --------------------------
// grid (8, 256, 2) x 256 thr: 8 warps = 8 tokens, grid.x=8 -> 64 per window.
__global__ void unwin_ln(const float* __restrict__ gam, const float* __restrict__ bet)
{
    int warp = threadIdx.x >> 5, lane = threadIdx.x & 31;
    int t = blockIdx.x * 8 + warp;
    int w = blockIdx.y, b = blockIdx.z;
    int i1 = w >> 6, i2 = (w >> 3) & 7, i3 = w & 7;
    int ms = t >> 4, mh = (t >> 2) & 3, mw = t & 3;
    int n = (i1 * 4 + ms) * 1024 + (i2 * 4 + mh) * 32 + (i3 * 4 + mw);
    float4 xv = *(const float4*)(g_lwin + (((size_t)b * 256 + w) * 64 + t) * 128 + lane * 4);
    size_t nrow = (size_t)b * 16384 + n;
    *(float4*)(g_l + nrow * 128 + lane * 4) = xv;
    warp_ln_split(xv, gam, bet, lane, (__nv_bfloat16*)g_a3_l + nrow * 384);
}

// -------------------- fp32 GEMM (small: rq/rk only) ------------------------
__global__ __launch_bounds__(256, 2)
void gemm_kernel(const float* __restrict__ A, const float* __restrict__ W,
                 const float* __restrict__ bias, const float* __restrict__ res,
                 float* __restrict__ C, int M, int N, int K, int act)
{
    __shared__ float As[16][132];
    __shared__ float Bs[16][132];
    const int bm = blockIdx.y * 128;
    const int bn = blockIdx.x * 128;
    const int tid = threadIdx.x;
    const int tx = tid & 15, ty = tid >> 4;
    const int arow = tid >> 1, acol = (tid & 1) * 8;
    const int brow = tid >> 4, bcol = (tid & 15) * 8;
    const float* Aptr = A + (size_t)(bm + arow) * K + acol;
    const float* Wptr = W + (size_t)brow * N + bn + bcol;
    float acc[8][8] = {};
    float4 a0 = *(const float4*)(Aptr);
    float4 a1 = *(const float4*)(Aptr + 4);
    float4 b0 = *(const float4*)(Wptr);
    float4 b1 = *(const float4*)(Wptr + 4);
    for (int k0 = 0; k0 < K; k0 += 16) {
        As[acol + 0][arow] = a0.x; As[acol + 1][arow] = a0.y;
        As[acol + 2][arow] = a0.z; As[acol + 3][arow] = a0.w;
        As[acol + 4][arow] = a1.x; As[acol + 5][arow] = a1.y;
        As[acol + 6][arow] = a1.z; As[acol + 7][arow] = a1.w;
        *(float4*)&Bs[brow][bcol] = b0;
        *(float4*)&Bs[brow][bcol + 4] = b1;
        __syncthreads();
        if (k0 + 16 < K) {
            a0 = *(const float4*)(Aptr + k0 + 16);
            a1 = *(const float4*)(Aptr + k0 + 20);
            b0 = *(const float4*)(Wptr + (size_t)(k0 + 16) * N);
            b1 = *(const float4*)(Wptr + (size_t)(k0 + 16) * N + 4);
        }
        #pragma unroll
        for (int kk = 0; kk < 16; kk++) {
            float a[8], b[8];
            *(float4*)(a)     = *(const float4*)&As[kk][ty * 4];
            *(float4*)(a + 4) = *(const float4*)&As[kk][64 + ty * 4];
            *(float4*)(b)     = *(const float4*)&Bs[kk][tx * 4];
            *(float4*)(b + 4) = *(const float4*)&Bs[kk][64 + tx * 4];
            #pragma unroll
            for (int i = 0; i < 8; i++)
                #pragma unroll
                for (int j = 0; j < 8; j++)
                    acc[i][j] += a[i] * b[j];
        }
        __syncthreads();
    }
    #pragma unroll
    for (int ih = 0; ih < 2; ih++)
        #pragma unroll
        for (int ii = 0; ii < 4; ii++) {
            int i = ih * 4 + ii;
            int row = bm + ih * 64 + ty * 4 + ii;
            #pragma unroll
            for (int jh = 0; jh < 2; jh++) {
                int col = bn + jh * 64 + tx * 4;
                float4 v;
                v.x = acc[i][jh * 4 + 0] + bias[col + 0];
                v.y = acc[i][jh * 4 + 1] + bias[col + 1];
                v.z = acc[i][jh * 4 + 2] + bias[col + 2];
                v.w = acc[i][jh * 4 + 3] + bias[col + 3];
                size_t idx = (size_t)row * N + col;
                if (res) {
                    float4 r4 = *(const float4*)(res + idx);
                    v.x += r4.x; v.y += r4.y; v.z += r4.z; v.w += r4.w;
                }
                *(float4*)(C + idx) = v;
            }
        }
}

// -------------------- global flash attention (split-bf16 epilogue) ---------
__global__ void attn_global(const float* __restrict__ qkv)
{
    const int b = blockIdx.z, h = blockIdx.y, q0 = blockIdx.x * 64;
    const int tid = threadIdx.x;
    const int q = tid >> 3, part = tid & 7;
    const float* base = qkv + (size_t)b * 2048 * 384;

    float4 qv[4];
    {
        const float4* qp = (const float4*)(base + (size_t)(q0 + q) * 384 + h * 16);
        #pragma unroll
        for (int i = 0; i < 4; i++) {
            qv[i] = qp[i];
            qv[i].x *= SCALE_DH; qv[i].y *= SCALE_DH;
            qv[i].z *= SCALE_DH; qv[i].w *= SCALE_DH;
        }
    }
    float m = -1e30f, l = 0.f;
    float o[16];
    #pragma unroll
    for (int d = 0; d < 16; d++) o[d] = 0.f;

    __shared__ float Ks[64][20];
    __shared__ float Vs[64][20];

    for (int c0 = 0; c0 < 2048; c0 += 64) {
        __syncthreads();
        {
            int mat = tid >> 8, idx = tid & 255;
            int r = idx >> 2, i = idx & 3;
            const float* row = base + (size_t)(c0 + r) * 384 + h * 16 + (mat ? 256 : 128);
            float* dst = mat ? Vs[r] : Ks[r];
            ((float4*)dst)[i] = *(const float4*)(row + i * 4);
        }
        __syncthreads();

        float s[8], cmax = -1e30f;
        #pragma unroll
        for (int j = 0; j < 8; j++) {
            int kr = part + j * 8;
            const float4* Kr = (const float4*)Ks[kr];
            float4 k0v = Kr[0], k1v = Kr[1], k2v = Kr[2], k3v = Kr[3];
            float a = qv[0].x*k0v.x + qv[0].y*k0v.y + qv[0].z*k0v.z + qv[0].w*k0v.w
                    + qv[1].x*k1v.x + qv[1].y*k1v.y + qv[1].z*k1v.z + qv[1].w*k1v.w
                    + qv[2].x*k2v.x + qv[2].y*k2v.y + qv[2].z*k2v.z + qv[2].w*k2v.w
                    + qv[3].x*k3v.x + qv[3].y*k3v.y + qv[3].z*k3v.z + qv[3].w*k3v.w;
            s[j] = a;
            cmax = fmaxf(cmax, a);
        }
        #pragma unroll
        for (int off = 4; off; off >>= 1)
            cmax = fmaxf(cmax, __shfl_xor_sync(0xffffffffu, cmax, off));
        float newm = fmaxf(m, cmax);
        float corr = __expf(m - newm);
        float p[8], psum = 0.f;
        #pragma unroll
        for (int j = 0; j < 8; j++) { p[j] = __expf(s[j] - newm); psum += p[j]; }
        #pragma unroll
        for (int off = 4; off; off >>= 1)
            psum += __shfl_xor_sync(0xffffffffu, psum, off);
        l = l * corr + psum;
        #pragma unroll
        for (int d = 0; d < 16; d++) o[d] *= corr;
        #pragma unroll
        for (int j = 0; j < 8; j++) {
            int kr = part + j * 8;
            const float4* Vr = (const float4*)Vs[kr];
            float4 v0 = Vr[0], v1 = Vr[1], v2 = Vr[2], v3 = Vr[3];
            float pj = p[j];
            o[0]  += pj * v0.x; o[1]  += pj * v0.y; o[2]  += pj * v0.z; o[3]  += pj * v0.w;
            o[4]  += pj * v1.x; o[5]  += pj * v1.y; o[6]  += pj * v1.z; o[7]  += pj * v1.w;
            o[8]  += pj * v2.x; o[9]  += pj * v2.y; o[10] += pj * v2.z; o[11] += pj * v2.w;
            o[12] += pj * v3.x; o[13] += pj * v3.y; o[14] += pj * v3.z; o[15] += pj * v3.w;
        }
        m = newm;
    }
    #pragma unroll
    for (int off = 4; off; off >>= 1)
        #pragma unroll
        for (int d = 0; d < 16; d++)
            o[d] += __shfl_xor_sync(0xffffffffu, o[d], off);
    float inv = 1.f / l;
    __nv_bfloat16* a3 = (__nv_bfloat16*)g_a3_attn;
    size_t row = (size_t)b * 2048 + q0 + q;
    int c = h * 16 + part * 2;
    #pragma unroll
    for (int d = 0; d < 2; d++) {
        __nv_bfloat16 hi, lo;
        split2(o[part * 2 + d] * inv, hi, lo);
        a3[row * 384 + c + d] = hi;
        a3[row * 384 + 128 + c + d] = hi;
        a3[row * 384 + 256 + c + d] = lo;
    }
}

// -------------------- window mean over global windows ----------------------
__global__ void gwin_kernel()
{
    int w = blockIdx.x, b = blockIdx.y, c = threadIdx.x;
    int i1 = w >> 6, i2 = (w >> 3) & 7, i3 = w & 7;
    float s = 0.f;
    #pragma unroll
    for (int ms = 0; ms < 2; ms++)
        #pragma unroll
        for (int mh = 0; mh < 2; mh++)
            #pragma unroll
            for (int mw = 0; mw < 2; mw++) {
                int n = (i1 * 2 + ms) * 256 + (i2 * 2 + mh) * 16 + (i3 * 2 + mw);
                s += g_xg4[((size_t)b * 2048 + n) * 128 + c];
            }
    g_gwin[((size_t)b * 256 + w) * 128 + c] = s * 0.125f;
}

// -------------------- routing: logits + top-4 indices ----------------------
__global__ void routing_kernel()
{
    int b = blockIdx.y, n = blockIdx.x, mIdx = threadIdx.x;
    __shared__ float lg[256];
    const float* qrow = g_qh + ((size_t)b * 256 + n) * 128;
    const float* krow = g_kh + ((size_t)b * 256 + mIdx) * 128;
    float acc = 0.f;
    #pragma unroll 8
    for (int c = 0; c < 128; c++) acc += qrow[c] * krow[c];
    lg[mIdx] = acc * SCALE_DIM;
    __syncthreads();
    if (mIdx == 0) {
        int* t = g_tidx + (b * 256 + n) * 4;
        for (int kk = 0; kk < 4; kk++) {
            float best = -1e30f; int bi = 0;
            for (int i = 0; i < 256; i++)
                if (lg[i] > best) { best = lg[i]; bi = i; }
            t[kk] = bi;
            lg[bi] = -1e30f;
        }
    }
}

// -------------------- window attention (split-bf16 epilogue) ---------------
__global__ void attn_win()
{
    const int w = blockIdx.x, h = blockIdx.y, b = blockIdx.z;
    const int tid = threadIdx.x;
    const float* base = g_qkvp + (size_t)(b * 256 + w) * 96 * 384;

    __shared__ float Ks[96][20];
    __shared__ float Vs[96][20];
    for (int e = tid; e < 384; e += 128) {
        int r = e >> 2, i = e & 3;
        const float* row = base + (size_t)r * 384 + h * 16;
        ((float4*)Ks[r])[i] = *(const float4*)(row + 128 + i * 4);
        ((float4*)Vs[r])[i] = *(const float4*)(row + 256 + i * 4);
    }
    __syncthreads();

    const int q = tid >> 1, part = tid & 1;
    float4 qv[4];
    {
        const float4* qp = (const float4*)(base + (size_t)q * 384 + h * 16);
        #pragma unroll
        for (int i = 0; i < 4; i++) {
            qv[i] = qp[i];
            qv[i].x *= SCALE_DIM; qv[i].y *= SCALE_DIM;
            qv[i].z *= SCALE_DIM; qv[i].w *= SCALE_DIM;
        }
    }
    float mx = -1e30f;
    for (int kr = part; kr < 96; kr += 2) {
        const float4* Kr = (const float4*)Ks[kr];
        float4 k0v = Kr[0], k1v = Kr[1], k2v = Kr[2], k3v = Kr[3];
        float a = qv[0].x*k0v.x + qv[0].y*k0v.y + qv[0].z*k0v.z + qv[0].w*k0v.w
                + qv[1].x*k1v.x + qv[1].y*k1v.y + qv[1].z*k1v.z + qv[1].w*k1v.w
                + qv[2].x*k2v.x + qv[2].y*k2v.y + qv[2].z*k2v.z + qv[2].w*k2v.w
                + qv[3].x*k3v.x + qv[3].y*k3v.y + qv[3].z*k3v.z + qv[3].w*k3v.w;
        mx = fmaxf(mx, a);
    }
    mx = fmaxf(mx, __shfl_xor_sync(0xffffffffu, mx, 1));
    float sum = 0.f;
    float o[16];
    #pragma unroll
    for (int d = 0; d < 16; d++) o[d] = 0.f;
    for (int kr = part; kr < 96; kr += 2) {
        const float4* Kr = (const float4*)Ks[kr];
        float4 k0v = Kr[0], k1v = Kr[1], k2v = Kr[2], k3v = Kr[3];
        float a = qv[0].x*k0v.x + qv[0].y*k0v.y + qv[0].z*k0v.z + qv[0].w*k0v.w
                + qv[1].x*k1v.x + qv[1].y*k1v.y + qv[1].z*k1v.z + qv[1].w*k1v.w
                + qv[2].x*k2v.x + qv[2].y*k2v.y + qv[2].z*k2v.z + qv[2].w*k2v.w
                + qv[3].x*k3v.x + qv[3].y*k3v.y + qv[3].z*k3v.z + qv[3].w*k3v.w;
        float p = __expf(a - mx);
        sum += p;
        const float4* Vr = (const float4*)Vs[kr];
        float4 v0 = Vr[0], v1 = Vr[1], v2 = Vr[2], v3 = Vr[3];
        o[0]  += p * v0.x; o[1]  += p * v0.y; o[2]  += p * v0.z; o[3]  += p * v0.w;
        o[4]  += p * v1.x; o[5]  += p * v1.y; o[6]  += p * v1.z; o[7]  += p * v1.w;
        o[8]  += p * v2.x; o[9]  += p * v2.y; o[10] += p * v2.z; o[11] += p * v2.w;
        o[12] += p * v3.x; o[13] += p * v3.y; o[14] += p * v3.z; o[15] += p * v3.w;
    }
    sum += __shfl_xor_sync(0xffffffffu, sum, 1);
    #pragma unroll
    for (int d = 0; d < 16; d++) o[d] += __shfl_xor_sync(0xffffffffu, o[d], 1);
    float inv = 1.f / sum;
    __nv_bfloat16* a3 = (__nv_bfloat16*)g_a3_awin;
    size_t row = ((size_t)(b * 256 + w)) * 64 + q;
    int cb = h * 16 + part * 8;
    #pragma unroll
    for (int d = 0; d < 8; d++) {
        __nv_bfloat16 hi, lo;
        split2(o[part * 8 + d] * inv, hi, lo);
        a3[row * 384 + cb + d] = hi;
        a3[row * 384 + 128 + cb + d] = hi;
        a3[row * 384 + 256 + cb + d] = lo;
    }
}

// ---------------------------------------------------------------------------
extern "C" void kernel_launch(void* const* d_in, const int* in_sizes, int n_in,
                              void* d_out, int out_size)
{
    const float* x_in    = (const float*)d_in[0];
    const float* x_g_in  = (const float*)d_in[1];
    const float* qkv_w   = (const float*)d_in[2];
    const float* qkv_b   = (const float*)d_in[3];
    const float* proj_w  = (const float*)d_in[4];
    const float* proj_b  = (const float*)d_in[5];
    const float* ln_g    = (const float*)d_in[6];
    const float* ln_b    = (const float*)d_in[7];
    const float* mlp_w1  = (const float*)d_in[8];
    const float* mlp_b1  = (const float*)d_in[9];
    const float* mlp_w2  = (const float*)d_in[10];
    const float* mlp_b2  = (const float*)d_in[11];
    const float* rq_w    = (const float*)d_in[12];
    const float* rq_b    = (const float*)d_in[13];
    const float* rk_w    = (const float*)d_in[14];
    const float* rk_b    = (const float*)d_in[15];
    const float* gqkv_w  = (const float*)d_in[16];
    const float* gqkv_b  = (const float*)d_in[17];
    const float* wo_w    = (const float*)d_in[18];
    const float* wo_b    = (const float*)d_in[19];
    const float* mlp2_w1 = (const float*)d_in[20];
    const float* mlp2_b1 = (const float*)d_in[21];
    const float* mlp2_w2 = (const float*)d_in[22];
    const float* mlp2_b2 = (const float*)d_in[23];
    float* out = (float*)d_out;

    cudaFuncSetAttribute(mma_gemm, cudaFuncAttributeMaxDynamicSharedMemorySize, GSM_BYTES);

    float *xg, *xl, *qkvg, *xg4, *gwin, *qh, *kh, *qkvp, *shortc, *lwin, *lbuf, *lfin;
    cudaGetSymbolAddress((void**)&xg,    g_xg);
    cudaGetSymbolAddress((void**)&xl,    g_xl);
    cudaGetSymbolAddress((void**)&qkvg,  g_qkvg);
    cudaGetSymbolAddress((void**)&xg4,   g_xg4);
    cudaGetSymbolAddress((void**)&gwin,  g_gwin);
    cudaGetSymbolAddress((void**)&qh,    g_qh);
    cudaGetSymbolAddress((void**)&kh,    g_kh);
    cudaGetSymbolAddress((void**)&qkvp,  g_qkvp);
    cudaGetSymbolAddress((void**)&shortc,g_short);
    cudaGetSymbolAddress((void**)&lwin,  g_lwin);
    cudaGetSymbolAddress((void**)&lbuf,  g_l);
    cudaGetSymbolAddress((void**)&lfin,  g_lfin);

    __nv_bfloat16 *a3g, *a3attn, *a3hid1, *a3sc, *a3awin, *a3l, *a3hid2;
    __nv_bfloat16 *w3qkv, *w3proj, *w3mlp1, *w3mlp2, *w3gqkv, *w3wo, *w3m2w1, *w3m2w2;
    cudaGetSymbolAddress((void**)&a3g,    g_a3_g);
    cudaGetSymbolAddress((void**)&a3attn, g_a3_attn);
    cudaGetSymbolAddress((void**)&a3hid1, g_a3_hid1);
    cudaGetSymbolAddress((void**)&a3sc,   g_a3_sc);
    cudaGetSymbolAddress((void**)&a3awin, g_a3_awin);
    cudaGetSymbolAddress((void**)&a3l,    g_a3_l);
    cudaGetSymbolAddress((void**)&a3hid2, g_a3_hid2);
    cudaGetSymbolAddress((void**)&w3qkv,  g_w3_qkv);
    cudaGetSymbolAddress((void**)&w3proj, g_w3_proj);
    cudaGetSymbolAddress((void**)&w3mlp1, g_w3_mlp1);
    cudaGetSymbolAddress((void**)&w3mlp2, g_w3_mlp2);
    cudaGetSymbolAddress((void**)&w3gqkv, g_w3_gqkv);
    cudaGetSymbolAddress((void**)&w3wo,   g_w3_wo);
    cudaGetSymbolAddress((void**)&w3m2w1, g_w3_m2w1);
    cudaGetSymbolAddress((void**)&w3m2w2, g_w3_m2w2);

    dim3 tb(32, 8);

    // 0) one merged weight-split launch
    w_split_all<<<dim3(256, 8), 256>>>(qkv_w, proj_w, mlp_w1, mlp_w2,
                                       gqkv_w, wo_w, mlp2_w1, mlp2_w2,
                                       w3qkv, w3proj, w3mlp1, w3mlp2,
                                       w3gqkv, w3wo, w3m2w1, w3m2w2);

    // 1-2) transposes to token-major
    transpose2d<<<dim3(2048 / 32, 4, 2), tb>>>(x_g_in, xg, 128, 2048);
    transpose2d<<<dim3(16384 / 32, 4, 2), tb>>>(x_in, xl, 128, 16384);

    // 3-9) global branch (launch #5 == attn_global for profiling)
    ln_split<<<512, 256>>>(xg, ln_g, ln_b, a3g, 4096);
    mma_gemm<<<dim3(3, 32), 256, GSM_BYTES>>>(a3g, w3qkv, qkv_b, nullptr, qkvg, nullptr, 384, 384, 0);
    attn_global<<<dim3(32, 8, 2), 512>>>(qkvg);
    mma_gemm<<<dim3(1, 32), 256, GSM_BYTES>>>(a3attn, w3proj, proj_b, xg, xg, nullptr, 128, 384, 0);
    ln_split<<<512, 256>>>(xg, ln_g, ln_b, a3g, 4096);
    mma_gemm<<<dim3(4, 32), 256, GSM_BYTES>>>(a3g, w3mlp1, mlp_b1, nullptr, nullptr, a3hid1, 512, 384, 2);
    mma_gemm<<<dim3(1, 32), 256, GSM_BYTES>>>(a3hid1, w3mlp2, mlp_b2, xg, xg4, nullptr, 128, 1536, 0);

    // routing
    gwin_kernel<<<dim3(256, 2), 128>>>();
    gemm_kernel<<<dim3(1, 4), 256>>>(gwin, rq_w, rq_b, nullptr, qh, 512, 128, 128, 0);
    gemm_kernel<<<dim3(1, 4), 256>>>(gwin, rk_w, rk_b, nullptr, kh, 512, 128, 128, 0);
    routing_kernel<<<dim3(256, 2), 256>>>();

    // fused gather+LN -> gqkv -> window attention
    gather_ln<<<dim3(12, 256, 2), 256>>>(ln_g, ln_b);
    mma_gemm<<<dim3(3, 384), 256, GSM_BYTES>>>(a3sc, w3gqkv, gqkv_b, nullptr, qkvp, nullptr, 384, 384, 0);
    attn_win<<<dim3(256, 8, 2), 128>>>();

    // wo(+shortcut) -> fused unwindow+LN -> MLP2(+res)
    mma_gemm<<<dim3(1, 256), 256, GSM_BYTES>>>(a3awin, w3wo, wo_b, shortc, lwin, nullptr, 128, 384, 0);
    unwin_ln<<<dim3(8, 256, 2), 256>>>(ln_g, ln_b);
    mma_gemm<<<dim3(4, 256), 256, GSM_BYTES>>>(a3l, w3m2w1, mlp2_b1, nullptr, nullptr, a3hid2, 512, 384, 2);
    mma_gemm<<<dim3(1, 256), 256, GSM_BYTES>>>(a3hid2, w3m2w2, mlp2_b2, lbuf, lfin, nullptr, 128, 1536, 0);

    // outputs
    transpose2d<<<dim3(4, 16384 / 32, 2), tb>>>(lfin, out, 16384, 128);
    transpose2d<<<dim3(4, 2048 / 32, 2), tb>>>(xg4, out + 2 * 128 * 16384, 2048, 128);
}